// round 16
// baseline (speedup 1.0000x reference)
#include <cuda_runtime.h>
#include <cuda_fp16.h>
#include <cstdint>

// ============================================================================
// Triplane + posenc + MLP(123->128->128->1), fused, sm_100 (warp-level HMMA).
// R16: R15 base (252.2) with B-only double-buffered k-pipeline in do_layer:
// B[k+1] (4 ldsm_x4) prefetched across the mma burst; A single-buffered.
// Peak frag regs 40 (+64 acc) vs R9's 48 — fits the 128-reg cap.
// ============================================================================
#define CCH   32
#define PH    256
#define PW    256
#define TILE_PTS 128
#define THREADS  256
#define GRID_PERSIST 296   // 148 SMs x 2 CTAs

// transposed planes: [3][256][256][32] fp16 (12.6 MB scratch, L2-resident)
__device__ __half g_planesHT[3u * 256u * 256u * 32u];

__device__ __forceinline__ uint32_t smem_u32(const void* p) {
    uint32_t a;
    asm("{ .reg .u64 t; cvta.to.shared.u64 t, %1; cvt.u32.u64 %0, t; }"
        : "=r"(a) : "l"(p));
    return a;
}

// Pair-local named barrier: warps (2m, 2m+1) sync via barrier id 1+m, 64 thr.
#define BAR_PAIR(wid) \
    asm volatile("bar.sync %0, 64;" :: "r"(1 + ((wid) >> 1)) : "memory")

// XOR-swizzled fp16 [128 x 128] tile: row stride 256B, 16B chunks XORed by row&7.
__device__ __forceinline__ uint32_t toff(int row, int col) {
    return ((uint32_t)row << 8) + ((((uint32_t)(col >> 3) ^ (row & 7))) << 4)
         + ((uint32_t)(col & 7) << 1);
}

__device__ __forceinline__ void ldsm_x4(uint32_t& r0, uint32_t& r1,
                                        uint32_t& r2, uint32_t& r3, uint32_t addr) {
    asm volatile("ldmatrix.sync.aligned.m8n8.x4.shared.b16 {%0,%1,%2,%3}, [%4];"
                 : "=r"(r0), "=r"(r1), "=r"(r2), "=r"(r3) : "r"(addr));
}
__device__ __forceinline__ void mma16816(float* d, uint32_t a0, uint32_t a1,
                                         uint32_t a2, uint32_t a3,
                                         uint32_t b0, uint32_t b1) {
    asm volatile(
        "mma.sync.aligned.m16n8k16.row.col.f32.f16.f16.f32 "
        "{%0,%1,%2,%3}, {%4,%5,%6,%7}, {%8,%9}, {%0,%1,%2,%3};"
        : "+f"(d[0]), "+f"(d[1]), "+f"(d[2]), "+f"(d[3])
        : "r"(a0), "r"(a1), "r"(a2), "r"(a3), "r"(b0), "r"(b1));
}

// ---------------------------------------------------------------------------
// SMEM layout (dynamic): 107520 B per CTA -> 2 CTAs/SM
// ---------------------------------------------------------------------------
#define OFF_IDX  0                      // int[384]
#define OFF_WGT  1536                   // uint4[384]: {w00,w01,w10,w11} half2-dup
#define OFF_BW   (OFF_WGT + 6144)       // float2[128] (b2, w3)      @7680
#define OFF_PART (OFF_BW + 1024)        // float[128] partials       @8704
#define OFF_H    9216                   // fp16 [128x128] swizzled; reused as A2
#define OFF_W1T  (OFF_H + 32768)
#define OFF_W2T  (OFF_W1T + 32768)
#define SMEM_TOTAL (OFF_W2T + 32768)    // 107520

// ---------------------------------------------------------------------------
// Prep: transpose planes [C,H,W] fp32 -> [H,W,C] fp16
// ---------------------------------------------------------------------------
__global__ void transpose_planes_kernel(const float* __restrict__ p0,
                                        const float* __restrict__ p1,
                                        const float* __restrict__ p2) {
    __shared__ float s[32][257];
    int b = blockIdx.x;          // 0..767
    int plane = b >> 8;
    int y = b & 255;
    const float* src = (plane == 0) ? p0 : ((plane == 1) ? p1 : p2);
    int x = threadIdx.x;
    #pragma unroll 4
    for (int c = 0; c < 32; ++c)
        s[c][x] = src[c * (PH * PW) + y * PW + x];
    __syncthreads();
    __half* dst = g_planesHT + ((size_t)plane << 21) + (size_t)y * (PW * CCH);
    for (int i = threadIdx.x; i < PW * CCH; i += 256)
        dst[i] = __float2half_rn(s[i & 31][i >> 5]);
}

// B fragments for one k-step (4 ldsm_x4).
__device__ __forceinline__ void load_B(uint32_t sB, int ncol, int lane, int k,
                                       uint32_t B[4][4]) {
    #pragma unroll
    for (int jn = 0; jn < 4; ++jn)
        ldsm_x4(B[jn][0], B[jn][1], B[jn][2], B[jn][3],
                sB + toff(ncol + jn * 16 + ((lane >> 4) << 3) + (lane & 7),
                          k * 16 + (((lane >> 3) & 1) << 3)));
}
// A fragments for one k-step (2 ldsm_x4).
__device__ __forceinline__ void load_A(uint32_t sA, int mrow, int lane, int k,
                                       uint32_t A[2][4]) {
    #pragma unroll
    for (int mi = 0; mi < 2; ++mi)
        ldsm_x4(A[mi][0], A[mi][1], A[mi][2], A[mi][3],
                sA + toff(mrow + mi * 16 + (lane & 15),
                          k * 16 + ((lane >> 4) << 3)));
}

// Issue the 16 mma of one k-step from a fragment set.
__device__ __forceinline__ void do_mmas(float* acc, uint32_t A[2][4], uint32_t B[4][4]) {
    #pragma unroll
    for (int jn = 0; jn < 4; ++jn) {
        #pragma unroll
        for (int mi = 0; mi < 2; ++mi) {
            mma16816(&acc[(mi * 8 + 2 * jn) * 4],
                     A[mi][0], A[mi][1], A[mi][2], A[mi][3], B[jn][0], B[jn][1]);
            mma16816(&acc[(mi * 8 + 2 * jn + 1) * 4],
                     A[mi][0], A[mi][1], A[mi][2], A[mi][3], B[jn][2], B[jn][3]);
        }
    }
}

// One MLP layer, B-only double-buffered k-pipeline.
__device__ __forceinline__ void do_layer(uint32_t sA, uint32_t sB, float* acc,
                                         int mrow, int ncol, int lane) {
    uint32_t B[2][4][4];
    uint32_t A[2][4];
    load_B(sB, ncol, lane, 0, B[0]);
    #pragma unroll
    for (int k = 0; k < 8; ++k) {
        int cur = k & 1;
        load_A(sA, mrow, lane, k, A);
        if (k < 7)
            load_B(sB, ncol, lane, k + 1, B[cur ^ 1]);
        do_mmas(acc, A, B[cur]);
    }
}

// ---------------------------------------------------------------------------
// Main fused persistent kernel
// ---------------------------------------------------------------------------
__global__ void __launch_bounds__(THREADS, 2)
triplane_mlp_kernel(const float* __restrict__ coords,
                    const float* __restrict__ W1, const float* __restrict__ b1,
                    const float* __restrict__ W2, const float* __restrict__ b2,
                    const float* __restrict__ W3, const float* __restrict__ b3,
                    float* __restrict__ out, int npts) {
    extern __shared__ char smem[];
    const uint32_t sbase = smem_u32(smem);
    const int tid  = threadIdx.x;
    const int wid  = tid >> 5;
    const int lane = tid & 31;

    int*    sIdx  = (int*)(smem + OFF_IDX);
    uint4*  sWgt  = (uint4*)(smem + OFF_WGT);
    float2* bw    = (float2*)(smem + OFF_BW);
    float*  sPart = (float*)(smem + OFF_PART);
    char* hT  = smem + OFF_H;

    // ---- Stage weights once (fp32 -> fp16 swizzled; b1 folded at col 123) ----
    for (int e = tid; e < 128 * 128; e += THREADS) {
        int row = e >> 7, col = e & 127;
        float v1 = (col < 123) ? W1[row * 123 + col]
                               : ((col == 123) ? b1[row] : 0.f);
        *(half*)(smem + OFF_W1T + toff(row, col)) = __float2half_rn(v1);
        *(half*)(smem + OFF_W2T + toff(row, col)) = __float2half_rn(W2[row * 128 + col]);
    }
    if (tid < 128)
        bw[tid] = make_float2(b2[tid], W3[tid]);
    const float b3v = b3[0];
    __syncthreads();

    const uint32_t sH  = sbase + OFF_H;
    const uint32_t sW1 = sbase + OFF_W1T;
    const uint32_t sW2 = sbase + OFF_W2T;
    // 4(M) x 2(N) warp grid
    const int mrow = (wid >> 1) * 32;
    const int ncol = (wid & 1) * 64;
    const int ntiles = npts >> 7;
    const int mypt = tid & 127;     // point handled in Phase A by this thread

    // coords prefetch (one tile ahead), both role halves
    float pcx = 0.f, pcy = 0.f, pcz = 0.f;
    if (blockIdx.x < ntiles) {
        size_t gi = (size_t)blockIdx.x * TILE_PTS + mypt;
        pcx = coords[gi * 3 + 0];
        pcy = coords[gi * 3 + 1];
        pcz = coords[gi * 3 + 2];
    }

    for (int tile = blockIdx.x; tile < ntiles; tile += gridDim.x) {
        // ---- Phase A (split roles, both halves busy) ----
        if (tid < 128) {
            // posenc cols 96..127 for point mypt, packed into 4x STS.128.
            union { half hv[32]; uint4 q[4]; } pk;
            const float c3[3] = {pcx, pcy, pcz};
            #pragma unroll
            for (int j = 0; j < 3; ++j)
                pk.hv[j] = __float2half_rn(c3[j]);
            #pragma unroll
            for (int fi = 0; fi < 4; ++fi) {
                float f = (float)(1 << fi);
                #pragma unroll
                for (int j = 0; j < 3; ++j) {
                    float a = c3[j] * f;
                    pk.hv[3 + fi * 6 + j] = __float2half_rn(__sinf(a));
                    pk.hv[6 + fi * 6 + j] = __float2half_rn(__cosf(a));
                }
            }
            pk.hv[27] = __float2half_rn(1.f);   // bias col 123
            pk.hv[28] = __float2half_rn(0.f);
            pk.hv[29] = __float2half_rn(0.f);
            pk.hv[30] = __float2half_rn(0.f);
            pk.hv[31] = __float2half_rn(0.f);
            #pragma unroll
            for (int c = 0; c < 4; ++c)
                *(uint4*)(hT + toff(mypt, 96 + c * 8)) = pk.q[c];
        } else {
            // sample params for point mypt, all 3 planes:
            // corner idx + 4 bilinear weights as duplicated-lane half2 (uint4)
            const float uu[3] = {pcx, pcy, pcx};
            const float vv[3] = {pcy, pcz, pcz};
            #pragma unroll
            for (int pl = 0; pl < 3; ++pl) {
                float fx = (uu[pl] + 1.f) * 127.5f;
                float fy = (vv[pl] + 1.f) * 127.5f;
                int x0 = (int)floorf(fx);
                int y0 = (int)floorf(fy);
                x0 = max(0, min(PW - 2, x0));
                y0 = max(0, min(PH - 2, y0));
                float wx1 = fx - (float)x0, wy1 = fy - (float)y0;
                float wx0 = 1.f - wx1, wy0 = 1.f - wy1;
                half2 h00 = __float2half2_rn(wx0 * wy0);
                half2 h01 = __float2half2_rn(wx1 * wy0);
                half2 h10 = __float2half2_rn(wx0 * wy1);
                half2 h11 = __float2half2_rn(wx1 * wy1);
                sIdx[mypt * 3 + pl] = y0 * PW + x0;
                sWgt[mypt * 3 + pl] = make_uint4(*(uint32_t*)&h00, *(uint32_t*)&h01,
                                                 *(uint32_t*)&h10, *(uint32_t*)&h11);
            }
        }
        // prefetch coords for the next tile this CTA will handle
        {
            int ntile = tile + gridDim.x;
            if (ntile < ntiles) {
                size_t gi = (size_t)ntile * TILE_PTS + mypt;
                pcx = coords[gi * 3 + 0];
                pcy = coords[gi * 3 + 1];
                pcz = coords[gi * 3 + 2];
            }
        }
        __syncthreads();

        // ---- Phase B: bilinear gather -> H cols 0..95 ----
        // 1536 items: point x plane x 8-channel chunk. Weights preloaded.
        #pragma unroll
        for (int itb = 0; itb < 6; ++itb) {
            int i = tid + itb * THREADS;
            int p = i / 12;
            int rem = i - p * 12;
            int pl = rem >> 2;
            int ch = rem & 3;
            int pp = p * 3 + pl;
            int idx = sIdx[pp];
            uint4 wq = sWgt[pp];            // LDS.128, quad-broadcast
            half2 w00 = *(half2*)&wq.x;
            half2 w01 = *(half2*)&wq.y;
            half2 w10 = *(half2*)&wq.z;
            half2 w11 = *(half2*)&wq.w;
            const __half* base = g_planesHT + ((size_t)pl << 21) + (size_t)idx * CCH + ch * 8;
            uint4 u00 = *(const uint4*)(base);
            uint4 u01 = *(const uint4*)(base + CCH);
            uint4 u10 = *(const uint4*)(base + PW * CCH);
            uint4 u11 = *(const uint4*)(base + PW * CCH + CCH);
            const half2* h00 = (const half2*)&u00;
            const half2* h01 = (const half2*)&u01;
            const half2* h10 = (const half2*)&u10;
            const half2* h11 = (const half2*)&u11;
            uint4 res;
            half2* hres = (half2*)&res;
            #pragma unroll
            for (int j = 0; j < 4; ++j) {
                half2 t = __hmul2(h00[j], w00);
                t = __hfma2(h01[j], w01, t);
                t = __hfma2(h10[j], w10, t);
                t = __hfma2(h11[j], w11, t);
                hres[j] = t;
            }
            *(uint4*)(hT + toff(p, pl * 32 + ch * 8)) = res;   // 16B aligned
        }
        __syncthreads();

        // ---- Layer 1: D1[32x64 per warp] = H @ W1^T ----
        float acc[64];
        #pragma unroll
        for (int j = 0; j < 64; ++j) acc[j] = 0.f;
        do_layer(sH, sW1, acc, mrow, ncol, lane);
        BAR_PAIR(wid);   // pair-local: only warps (2m,2m+1) touch rows [32m,32m+32)

        // relu -> fp16 -> write A2 into H buffer
        #pragma unroll
        for (int mi = 0; mi < 2; ++mi) {
            int r0 = mrow + mi * 16 + (lane >> 2);
            #pragma unroll
            for (int j = 0; j < 8; ++j) {
                int c = ncol + j * 8 + (lane & 3) * 2;
                const float* a4 = &acc[(mi * 8 + j) * 4];
                *(half2*)(hT + toff(r0, c)) =
                    __floats2half2_rn(fmaxf(a4[0], 0.f), fmaxf(a4[1], 0.f));
                *(half2*)(hT + toff(r0 + 8, c)) =
                    __floats2half2_rn(fmaxf(a4[2], 0.f), fmaxf(a4[3], 0.f));
            }
        }
        BAR_PAIR(wid);   // pair-local: layer-2 A reads the same private rows

        // ---- Layer 2: D2 = A2 @ W2^T ----
        #pragma unroll
        for (int j = 0; j < 64; ++j) acc[j] = 0.f;
        do_layer(sH, sW2, acc, mrow, ncol, lane);

        // ---- Epilogue: out = relu(D2 + b2) . W3 + b3 ----
        {
            float part[4];  // [mi*2 + half]
            #pragma unroll
            for (int q = 0; q < 4; ++q) part[q] = 0.f;
            #pragma unroll
            for (int mi = 0; mi < 2; ++mi) {
                #pragma unroll
                for (int j = 0; j < 8; ++j) {
                    int c = ncol + j * 8 + (lane & 3) * 2;
                    float2 bw0 = bw[c];
                    float2 bw1 = bw[c + 1];
                    const float* a4 = &acc[(mi * 8 + j) * 4];
                    part[mi * 2 + 0] += fmaxf(a4[0] + bw0.x, 0.f) * bw0.y
                                      + fmaxf(a4[1] + bw1.x, 0.f) * bw1.y;
                    part[mi * 2 + 1] += fmaxf(a4[2] + bw0.x, 0.f) * bw0.y
                                      + fmaxf(a4[3] + bw1.x, 0.f) * bw1.y;
                }
            }
            #pragma unroll
            for (int q = 0; q < 4; ++q) {
                part[q] += __shfl_xor_sync(0xFFFFFFFF, part[q], 1);
                part[q] += __shfl_xor_sync(0xFFFFFFFF, part[q], 2);
            }
            // cross-warp combine: odd-N warp writes partials, even-N warp sums+stores
            if ((wid & 1) && (lane & 3) == 0) {
                #pragma unroll
                for (int q = 0; q < 4; ++q) {
                    int row = mrow + (q >> 1) * 16 + (q & 1) * 8 + (lane >> 2);
                    sPart[row] = part[q];
                }
            }
            // CTA-wide: pairs exchange partials AND this fences H for the next
            // tile's gather/posenc overwrite (which is cross-pair).
            __syncthreads();
            if (!(wid & 1) && (lane & 3) == 0) {
                size_t g = (size_t)tile * TILE_PTS;
                #pragma unroll
                for (int q = 0; q < 4; ++q) {
                    int row = mrow + (q >> 1) * 16 + (q & 1) * 8 + (lane >> 2);
                    out[g + row] = part[q] + sPart[row] + b3v;
                }
            }
        }
    }
}

// ---------------------------------------------------------------------------
// Launch: inputs 0 coords, 1-3 planes, 4 W1, 5 b1, 6 W2, 7 b2, 8 W3, 9 b3
// ---------------------------------------------------------------------------
extern "C" void kernel_launch(void* const* d_in, const int* in_sizes, int n_in,
                              void* d_out, int out_size) {
    const float* coords = (const float*)d_in[0];
    const float* p0 = (const float*)d_in[1];
    const float* p1 = (const float*)d_in[2];
    const float* p2 = (const float*)d_in[3];
    const float* W1 = (const float*)d_in[4];
    const float* b1 = (const float*)d_in[5];
    const float* W2 = (const float*)d_in[6];
    const float* b2 = (const float*)d_in[7];
    const float* W3 = (const float*)d_in[8];
    const float* b3 = (const float*)d_in[9];
    float* out = (float*)d_out;
    int npts = out_size;

    transpose_planes_kernel<<<3 * PH, 256>>>(p0, p1, p2);

    cudaFuncSetAttribute(triplane_mlp_kernel,
                         cudaFuncAttributeMaxDynamicSharedMemorySize, SMEM_TOTAL);
    triplane_mlp_kernel<<<GRID_PERSIST, THREADS, SMEM_TOTAL>>>(
        coords, W1, b1, W2, b2, W3, b3, out, npts);
}

// round 17
// speedup vs baseline: 1.0284x; 1.0284x over previous
#include <cuda_runtime.h>
#include <cuda_fp16.h>
#include <cstdint>

// ============================================================================
// Triplane + posenc + MLP(123->128->128->1), fused, sm_100 (warp-level HMMA).
// R17: R15 base (best: 252.2) + global work-stealing tile scheduler
// (atomic counter; removes 27-vs-28 static imbalance and CTA-spread tail).
// R16's B-only double-buffer reverted (regressed).
// ============================================================================
#define CCH   32
#define PH    256
#define PW    256
#define TILE_PTS 128
#define THREADS  256
#define GRID_PERSIST 296   // 148 SMs x 2 CTAs

// transposed planes: [3][256][256][32] fp16 (12.6 MB scratch, L2-resident)
__device__ __half g_planesHT[3u * 256u * 256u * 32u];
__device__ int g_tileCtr;

__global__ void reset_ctr_kernel() { g_tileCtr = 0; }

__device__ __forceinline__ uint32_t smem_u32(const void* p) {
    uint32_t a;
    asm("{ .reg .u64 t; cvta.to.shared.u64 t, %1; cvt.u32.u64 %0, t; }"
        : "=r"(a) : "l"(p));
    return a;
}

// Pair-local named barrier: warps (2m, 2m+1) sync via barrier id 1+m, 64 thr.
#define BAR_PAIR(wid) \
    asm volatile("bar.sync %0, 64;" :: "r"(1 + ((wid) >> 1)) : "memory")

// XOR-swizzled fp16 [128 x 128] tile: row stride 256B, 16B chunks XORed by row&7.
__device__ __forceinline__ uint32_t toff(int row, int col) {
    return ((uint32_t)row << 8) + ((((uint32_t)(col >> 3) ^ (row & 7))) << 4)
         + ((uint32_t)(col & 7) << 1);
}

__device__ __forceinline__ void ldsm_x4(uint32_t& r0, uint32_t& r1,
                                        uint32_t& r2, uint32_t& r3, uint32_t addr) {
    asm volatile("ldmatrix.sync.aligned.m8n8.x4.shared.b16 {%0,%1,%2,%3}, [%4];"
                 : "=r"(r0), "=r"(r1), "=r"(r2), "=r"(r3) : "r"(addr));
}
__device__ __forceinline__ void mma16816(float* d, uint32_t a0, uint32_t a1,
                                         uint32_t a2, uint32_t a3,
                                         uint32_t b0, uint32_t b1) {
    asm volatile(
        "mma.sync.aligned.m16n8k16.row.col.f32.f16.f16.f32 "
        "{%0,%1,%2,%3}, {%4,%5,%6,%7}, {%8,%9}, {%0,%1,%2,%3};"
        : "+f"(d[0]), "+f"(d[1]), "+f"(d[2]), "+f"(d[3])
        : "r"(a0), "r"(a1), "r"(a2), "r"(a3), "r"(b0), "r"(b1));
}

// ---------------------------------------------------------------------------
// SMEM layout (dynamic): 107648 B per CTA -> 2 CTAs/SM
// ---------------------------------------------------------------------------
#define OFF_IDX  0                      // int[384]
#define OFF_WGT  1536                   // uint4[384]: {w00,w01,w10,w11} half2-dup
#define OFF_BW   (OFF_WGT + 6144)       // float2[128] (b2, w3)      @7680
#define OFF_PART (OFF_BW + 1024)        // float[128] partials       @8704
#define OFF_NEXT (OFF_PART + 512)       // int: next stolen tile     @9216
#define OFF_H    9344                   // fp16 [128x128] swizzled; reused as A2
#define OFF_W1T  (OFF_H + 32768)
#define OFF_W2T  (OFF_W1T + 32768)
#define SMEM_TOTAL (OFF_W2T + 32768)    // 107648

// ---------------------------------------------------------------------------
// Prep: transpose planes [C,H,W] fp32 -> [H,W,C] fp16
// ---------------------------------------------------------------------------
__global__ void transpose_planes_kernel(const float* __restrict__ p0,
                                        const float* __restrict__ p1,
                                        const float* __restrict__ p2) {
    __shared__ float s[32][257];
    int b = blockIdx.x;          // 0..767
    int plane = b >> 8;
    int y = b & 255;
    const float* src = (plane == 0) ? p0 : ((plane == 1) ? p1 : p2);
    int x = threadIdx.x;
    #pragma unroll 4
    for (int c = 0; c < 32; ++c)
        s[c][x] = src[c * (PH * PW) + y * PW + x];
    __syncthreads();
    __half* dst = g_planesHT + ((size_t)plane << 21) + (size_t)y * (PW * CCH);
    for (int i = threadIdx.x; i < PW * CCH; i += 256)
        dst[i] = __float2half_rn(s[i & 31][i >> 5]);
}

// Load all fragments for one k-step.
__device__ __forceinline__ void load_frags(uint32_t sA, uint32_t sB,
                                           int mrow, int ncol, int lane, int k,
                                           uint32_t A[2][4], uint32_t B[4][4]) {
    #pragma unroll
    for (int mi = 0; mi < 2; ++mi)
        ldsm_x4(A[mi][0], A[mi][1], A[mi][2], A[mi][3],
                sA + toff(mrow + mi * 16 + (lane & 15),
                          k * 16 + ((lane >> 4) << 3)));
    #pragma unroll
    for (int jn = 0; jn < 4; ++jn)
        ldsm_x4(B[jn][0], B[jn][1], B[jn][2], B[jn][3],
                sB + toff(ncol + jn * 16 + ((lane >> 4) << 3) + (lane & 7),
                          k * 16 + (((lane >> 3) & 1) << 3)));
}

// Issue the 16 mma of one k-step from a fragment set.
__device__ __forceinline__ void do_mmas(float* acc, uint32_t A[2][4], uint32_t B[4][4]) {
    #pragma unroll
    for (int jn = 0; jn < 4; ++jn) {
        #pragma unroll
        for (int mi = 0; mi < 2; ++mi) {
            mma16816(&acc[(mi * 8 + 2 * jn) * 4],
                     A[mi][0], A[mi][1], A[mi][2], A[mi][3], B[jn][0], B[jn][1]);
            mma16816(&acc[(mi * 8 + 2 * jn + 1) * 4],
                     A[mi][0], A[mi][1], A[mi][2], A[mi][3], B[jn][2], B[jn][3]);
        }
    }
}

// One MLP layer, k-pipelined: acc[2 m][8 n][4] += A(sA) @ B(sB)^T
__device__ __forceinline__ void do_layer(uint32_t sA, uint32_t sB, float* acc,
                                         int mrow, int ncol, int lane) {
    uint32_t A[2][2][4], B[2][4][4];
    load_frags(sA, sB, mrow, ncol, lane, 0, A[0], B[0]);
    #pragma unroll
    for (int k = 0; k < 8; ++k) {
        int cur = k & 1;
        if (k < 7)
            load_frags(sA, sB, mrow, ncol, lane, k + 1, A[cur ^ 1], B[cur ^ 1]);
        do_mmas(acc, A[cur], B[cur]);
    }
}

// ---------------------------------------------------------------------------
// Main fused persistent kernel (work-stealing scheduler)
// ---------------------------------------------------------------------------
__global__ void __launch_bounds__(THREADS, 2)
triplane_mlp_kernel(const float* __restrict__ coords,
                    const float* __restrict__ W1, const float* __restrict__ b1,
                    const float* __restrict__ W2, const float* __restrict__ b2,
                    const float* __restrict__ W3, const float* __restrict__ b3,
                    float* __restrict__ out, int npts) {
    extern __shared__ char smem[];
    const uint32_t sbase = smem_u32(smem);
    const int tid  = threadIdx.x;
    const int wid  = tid >> 5;
    const int lane = tid & 31;

    int*    sIdx  = (int*)(smem + OFF_IDX);
    uint4*  sWgt  = (uint4*)(smem + OFF_WGT);
    float2* bw    = (float2*)(smem + OFF_BW);
    float*  sPart = (float*)(smem + OFF_PART);
    int*    sNext = (int*)(smem + OFF_NEXT);
    char* hT  = smem + OFF_H;

    // ---- Stage weights once (fp32 -> fp16 swizzled; b1 folded at col 123) ----
    for (int e = tid; e < 128 * 128; e += THREADS) {
        int row = e >> 7, col = e & 127;
        float v1 = (col < 123) ? W1[row * 123 + col]
                               : ((col == 123) ? b1[row] : 0.f);
        *(half*)(smem + OFF_W1T + toff(row, col)) = __float2half_rn(v1);
        *(half*)(smem + OFF_W2T + toff(row, col)) = __float2half_rn(W2[row * 128 + col]);
    }
    if (tid < 128)
        bw[tid] = make_float2(b2[tid], W3[tid]);
    if (tid == 0)
        *sNext = atomicAdd(&g_tileCtr, 1);   // steal first tile
    const float b3v = b3[0];
    __syncthreads();

    const uint32_t sH  = sbase + OFF_H;
    const uint32_t sW1 = sbase + OFF_W1T;
    const uint32_t sW2 = sbase + OFF_W2T;
    // 4(M) x 2(N) warp grid
    const int mrow = (wid >> 1) * 32;
    const int ncol = (wid & 1) * 64;
    const int ntiles = npts >> 7;
    const int mypt = tid & 127;     // point handled in Phase A by this thread

    int tile = *sNext;
    // coords prefetch for the first tile
    float pcx = 0.f, pcy = 0.f, pcz = 0.f;
    if (tile < ntiles) {
        size_t gi = (size_t)tile * TILE_PTS + mypt;
        pcx = coords[gi * 3 + 0];
        pcy = coords[gi * 3 + 1];
        pcz = coords[gi * 3 + 2];
    }

    while (tile < ntiles) {
        // ---- Phase A (split roles, both halves busy) ----
        if (tid < 128) {
            // posenc cols 96..127 for point mypt, packed into 4x STS.128.
            union { half hv[32]; uint4 q[4]; } pk;
            const float c3[3] = {pcx, pcy, pcz};
            #pragma unroll
            for (int j = 0; j < 3; ++j)
                pk.hv[j] = __float2half_rn(c3[j]);
            #pragma unroll
            for (int fi = 0; fi < 4; ++fi) {
                float f = (float)(1 << fi);
                #pragma unroll
                for (int j = 0; j < 3; ++j) {
                    float a = c3[j] * f;
                    pk.hv[3 + fi * 6 + j] = __float2half_rn(__sinf(a));
                    pk.hv[6 + fi * 6 + j] = __float2half_rn(__cosf(a));
                }
            }
            pk.hv[27] = __float2half_rn(1.f);   // bias col 123
            pk.hv[28] = __float2half_rn(0.f);
            pk.hv[29] = __float2half_rn(0.f);
            pk.hv[30] = __float2half_rn(0.f);
            pk.hv[31] = __float2half_rn(0.f);
            #pragma unroll
            for (int c = 0; c < 4; ++c)
                *(uint4*)(hT + toff(mypt, 96 + c * 8)) = pk.q[c];
            if (tid == 0)
                *sNext = atomicAdd(&g_tileCtr, 1);   // steal next tile
        } else {
            // sample params for point mypt, all 3 planes:
            // corner idx + 4 bilinear weights as duplicated-lane half2 (uint4)
            const float uu[3] = {pcx, pcy, pcx};
            const float vv[3] = {pcy, pcz, pcz};
            #pragma unroll
            for (int pl = 0; pl < 3; ++pl) {
                float fx = (uu[pl] + 1.f) * 127.5f;
                float fy = (vv[pl] + 1.f) * 127.5f;
                int x0 = (int)floorf(fx);
                int y0 = (int)floorf(fy);
                x0 = max(0, min(PW - 2, x0));
                y0 = max(0, min(PH - 2, y0));
                float wx1 = fx - (float)x0, wy1 = fy - (float)y0;
                float wx0 = 1.f - wx1, wy0 = 1.f - wy1;
                half2 h00 = __float2half2_rn(wx0 * wy0);
                half2 h01 = __float2half2_rn(wx1 * wy0);
                half2 h10 = __float2half2_rn(wx0 * wy1);
                half2 h11 = __float2half2_rn(wx1 * wy1);
                sIdx[mypt * 3 + pl] = y0 * PW + x0;
                sWgt[mypt * 3 + pl] = make_uint4(*(uint32_t*)&h00, *(uint32_t*)&h01,
                                                 *(uint32_t*)&h10, *(uint32_t*)&h11);
            }
        }
        __syncthreads();

        // next tile id now visible; prefetch its coords (overlaps gather+MMA)
        const int ntile = *sNext;
        if (ntile < ntiles) {
            size_t gi = (size_t)ntile * TILE_PTS + mypt;
            pcx = coords[gi * 3 + 0];
            pcy = coords[gi * 3 + 1];
            pcz = coords[gi * 3 + 2];
        }

        // ---- Phase B: bilinear gather -> H cols 0..95 ----
        // 1536 items: point x plane x 8-channel chunk. Weights preloaded.
        #pragma unroll
        for (int itb = 0; itb < 6; ++itb) {
            int i = tid + itb * THREADS;
            int p = i / 12;
            int rem = i - p * 12;
            int pl = rem >> 2;
            int ch = rem & 3;
            int pp = p * 3 + pl;
            int idx = sIdx[pp];
            uint4 wq = sWgt[pp];            // LDS.128, quad-broadcast
            half2 w00 = *(half2*)&wq.x;
            half2 w01 = *(half2*)&wq.y;
            half2 w10 = *(half2*)&wq.z;
            half2 w11 = *(half2*)&wq.w;
            const __half* base = g_planesHT + ((size_t)pl << 21) + (size_t)idx * CCH + ch * 8;
            uint4 u00 = *(const uint4*)(base);
            uint4 u01 = *(const uint4*)(base + CCH);
            uint4 u10 = *(const uint4*)(base + PW * CCH);
            uint4 u11 = *(const uint4*)(base + PW * CCH + CCH);
            const half2* h00 = (const half2*)&u00;
            const half2* h01 = (const half2*)&u01;
            const half2* h10 = (const half2*)&u10;
            const half2* h11 = (const half2*)&u11;
            uint4 res;
            half2* hres = (half2*)&res;
            #pragma unroll
            for (int j = 0; j < 4; ++j) {
                half2 t = __hmul2(h00[j], w00);
                t = __hfma2(h01[j], w01, t);
                t = __hfma2(h10[j], w10, t);
                t = __hfma2(h11[j], w11, t);
                hres[j] = t;
            }
            *(uint4*)(hT + toff(p, pl * 32 + ch * 8)) = res;   // 16B aligned
        }
        __syncthreads();

        // ---- Layer 1: D1[32x64 per warp] = H @ W1^T ----
        float acc[64];
        #pragma unroll
        for (int j = 0; j < 64; ++j) acc[j] = 0.f;
        do_layer(sH, sW1, acc, mrow, ncol, lane);
        BAR_PAIR(wid);   // pair-local: only warps (2m,2m+1) touch rows [32m,32m+32)

        // relu -> fp16 -> write A2 into H buffer
        #pragma unroll
        for (int mi = 0; mi < 2; ++mi) {
            int r0 = mrow + mi * 16 + (lane >> 2);
            #pragma unroll
            for (int j = 0; j < 8; ++j) {
                int c = ncol + j * 8 + (lane & 3) * 2;
                const float* a4 = &acc[(mi * 8 + j) * 4];
                *(half2*)(hT + toff(r0, c)) =
                    __floats2half2_rn(fmaxf(a4[0], 0.f), fmaxf(a4[1], 0.f));
                *(half2*)(hT + toff(r0 + 8, c)) =
                    __floats2half2_rn(fmaxf(a4[2], 0.f), fmaxf(a4[3], 0.f));
            }
        }
        BAR_PAIR(wid);   // pair-local: layer-2 A reads the same private rows

        // ---- Layer 2: D2 = A2 @ W2^T ----
        #pragma unroll
        for (int j = 0; j < 64; ++j) acc[j] = 0.f;
        do_layer(sH, sW2, acc, mrow, ncol, lane);

        // ---- Epilogue: out = relu(D2 + b2) . W3 + b3 ----
        {
            float part[4];  // [mi*2 + half]
            #pragma unroll
            for (int q = 0; q < 4; ++q) part[q] = 0.f;
            #pragma unroll
            for (int mi = 0; mi < 2; ++mi) {
                #pragma unroll
                for (int j = 0; j < 8; ++j) {
                    int c = ncol + j * 8 + (lane & 3) * 2;
                    float2 bw0 = bw[c];
                    float2 bw1 = bw[c + 1];
                    const float* a4 = &acc[(mi * 8 + j) * 4];
                    part[mi * 2 + 0] += fmaxf(a4[0] + bw0.x, 0.f) * bw0.y
                                      + fmaxf(a4[1] + bw1.x, 0.f) * bw1.y;
                    part[mi * 2 + 1] += fmaxf(a4[2] + bw0.x, 0.f) * bw0.y
                                      + fmaxf(a4[3] + bw1.x, 0.f) * bw1.y;
                }
            }
            #pragma unroll
            for (int q = 0; q < 4; ++q) {
                part[q] += __shfl_xor_sync(0xFFFFFFFF, part[q], 1);
                part[q] += __shfl_xor_sync(0xFFFFFFFF, part[q], 2);
            }
            // cross-warp combine: odd-N warp writes partials, even-N warp sums+stores
            if ((wid & 1) && (lane & 3) == 0) {
                #pragma unroll
                for (int q = 0; q < 4; ++q) {
                    int row = mrow + (q >> 1) * 16 + (q & 1) * 8 + (lane >> 2);
                    sPart[row] = part[q];
                }
            }
            // CTA-wide: pairs exchange partials AND this fences H for the next
            // tile's gather/posenc overwrite (which is cross-pair).
            __syncthreads();
            if (!(wid & 1) && (lane & 3) == 0) {
                size_t g = (size_t)tile * TILE_PTS;
                #pragma unroll
                for (int q = 0; q < 4; ++q) {
                    int row = mrow + (q >> 1) * 16 + (q & 1) * 8 + (lane >> 2);
                    out[g + row] = part[q] + sPart[row] + b3v;
                }
            }
        }
        tile = ntile;
    }
}

// ---------------------------------------------------------------------------
// Launch: inputs 0 coords, 1-3 planes, 4 W1, 5 b1, 6 W2, 7 b2, 8 W3, 9 b3
// ---------------------------------------------------------------------------
extern "C" void kernel_launch(void* const* d_in, const int* in_sizes, int n_in,
                              void* d_out, int out_size) {
    const float* coords = (const float*)d_in[0];
    const float* p0 = (const float*)d_in[1];
    const float* p1 = (const float*)d_in[2];
    const float* p2 = (const float*)d_in[3];
    const float* W1 = (const float*)d_in[4];
    const float* b1 = (const float*)d_in[5];
    const float* W2 = (const float*)d_in[6];
    const float* b2 = (const float*)d_in[7];
    const float* W3 = (const float*)d_in[8];
    const float* b3 = (const float*)d_in[9];
    float* out = (float*)d_out;
    int npts = out_size;

    reset_ctr_kernel<<<1, 1>>>();
    transpose_planes_kernel<<<3 * PH, 256>>>(p0, p1, p2);

    cudaFuncSetAttribute(triplane_mlp_kernel,
                         cudaFuncAttributeMaxDynamicSharedMemorySize, SMEM_TOTAL);
    triplane_mlp_kernel<<<GRID_PERSIST, THREADS, SMEM_TOTAL>>>(
        coords, W1, b1, W2, b2, W3, b3, out, npts);
}